// round 4
// baseline (speedup 1.0000x reference)
#include <cuda_runtime.h>
#include <cstdint>

// CTC loss, probability-domain forward DP, per-lane block-float exponents.
// R4: coalesced LDG.128 row loads + register-shuffle gather (replaces the
// scattered 3-LDG-per-step gather that caused ~30 L1 wavefronts/step).
// B=512, T=512, C=128, L=64, S=129, blank=127. One warp per batch element.
// Lane l owns states 4l..4l+3 (a0..a3); lane 31 also owns s=128 (a4).

#define CTC_B 512
#define CTC_T 512
#define CTC_C 128
#define CTC_L 64
#define PF 16              // row-pipeline depth (LDG.128s in flight)
#define RS 8               // rescale period (steps)

__global__ __launch_bounds__(32) void ctc_kernel(
    const int* __restrict__ y_true,
    const float* __restrict__ y_pred,
    float* __restrict__ out)
{
    const float EPS = 1e-7f;
    const unsigned FULL = 0xffffffffu;
    const int b    = blockIdx.x;
    const int lane = threadIdx.x;

    // labels for odd states s=4l+1 (label 2l) and s=4l+3 (label 2l+1)
    const int* lrow = y_true + b * CTC_L;
    const int lab1 = lrow[2 * lane];
    const int lab3 = lrow[2 * lane + 1];
    const int prev1 = (lane > 0) ? lrow[2 * lane - 1] : -1;
    const bool allow1 = (lane > 0) && (lab1 != prev1);
    const bool allow3 = (lab3 != lab1);

    // gather descriptors: source lane + 2 select bits each
    const int  s1 = lab1 >> 2;  const bool k1b0 = lab1 & 1, k1b1 = lab1 & 2;
    const int  s3 = lab3 >> 2;  const bool k3b0 = lab3 & 1, k3b1 = lab3 & 2;

    // coalesced row pointer: lane l reads cols 4l..4l+3 of each row
    const float4* rowp = reinterpret_cast<const float4*>(
        y_pred + (size_t)b * CTC_T * CTC_C) + lane;   // stride 32 float4 per row

    float4 R[PF];
#pragma unroll
    for (int j = 0; j < PF; ++j) R[j] = rowp[j * 32];

    // virtual pre-init: a0=1 on lane 0 makes step t=0 yield the reference init
    float a0 = (lane == 0) ? 1.0f : 0.0f;
    float a1 = 0.0f, a2 = 0.0f, a3 = 0.0f, a4 = 0.0f;
    int   E  = 0;                               // alpha = a * 2^E (per lane)
    float f  = (lane == 0) ? 0.0f : 1.0f;       // neighbor re-basing factor

    for (int tb = 0; tb < CTC_T; tb += PF) {
#pragma unroll
        for (int j = 0; j < PF; ++j) {
            const int t = tb + j;
            const float4 cur = R[j];
            if (t + PF < CTC_T) R[j] = rowp[(t + PF) * 32];   // refill slot

            // blank prob: col 127 = lane 31's .w
            const float pb = __shfl_sync(FULL, cur.w, 31) + EPS;

            // gather p[lab1]
            float g0 = __shfl_sync(FULL, cur.x, s1);
            float g1 = __shfl_sync(FULL, cur.y, s1);
            float g2 = __shfl_sync(FULL, cur.z, s1);
            float g3 = __shfl_sync(FULL, cur.w, s1);
            float lo = k1b0 ? g1 : g0;
            float hi = k1b0 ? g3 : g2;
            const float p1 = (k1b1 ? hi : lo) + EPS;

            // gather p[lab3]
            float h0 = __shfl_sync(FULL, cur.x, s3);
            float h1 = __shfl_sync(FULL, cur.y, s3);
            float h2 = __shfl_sync(FULL, cur.z, s3);
            float h3 = __shfl_sync(FULL, cur.w, s3);
            float lo3 = k3b0 ? h1 : h0;
            float hi3 = k3b0 ? h3 : h2;
            const float p3 = (k3b1 ? hi3 : lo3) + EPS;

            // neighbor alpha[4l-1], re-based into my exponent frame
            const float am1 = __shfl_up_sync(FULL, a3, 1) * f;  // lane0: f=0

            const float n0 = (a0 + am1) * pb;                         // s=4l   (blank)
            const float n1 = (a1 + a0 + (allow1 ? am1 : 0.0f)) * p1;  // s=4l+1
            const float n2 = (a2 + a1) * pb;                          // s=4l+2 (blank)
            const float n3 = (a3 + a2 + (allow3 ? a1 : 0.0f)) * p3;   // s=4l+3
            const float n4 = (a4 + a3) * pb;                          // s=128 (lane31)
            a0 = n0; a1 = n1; a2 = n2; a3 = n3; a4 = n4;

            if ((j & (RS - 1)) == (RS - 1)) {
                // ---- per-lane power-of-2 rescale ----
                float lm = fmaxf(fmaxf(a0, a1), fmaxf(a2, a3));
                lm = fmaxf(lm, a4);
                int e = (int)(__float_as_uint(lm) >> 23) - 127;
                const bool zero = (lm == 0.0f);
                if (zero) e = 0;
                const float sc = __uint_as_float((unsigned)(127 - e) << 23); // 2^-e
                a0 *= sc; a1 *= sc; a2 *= sc; a3 *= sc; a4 *= sc;
                E += e;
                // all-zero lanes (ahead of the DP wavefront) adopt neighbor's frame
                const int Ep = __shfl_up_sync(FULL, E, 1);
                if (zero && lane > 0) E = Ep;
                // neighbor re-basing factor for the next RS steps
                const int Ep2 = __shfl_up_sync(FULL, E, 1);
                int d = Ep2 - E;
                d = max(-126, min(126, d));
                f = __uint_as_float((unsigned)(127 + d) << 23);  // 2^d
                if (lane == 0) f = 0.0f;
            }
        }
    }

    if (lane == 31) {
        // P_total = alpha_{T-1}[S-1] + alpha_{T-1}[S-2] = (a4 + a3) * 2^E
        const float p = a4 + a3;
        out[b] = -(__logf(p) + (float)E * 0.69314718055994530942f);
    }
}

extern "C" void kernel_launch(void* const* d_in, const int* in_sizes, int n_in,
                              void* d_out, int out_size) {
    const int*   y_true = (const int*)d_in[0];
    const float* y_pred = (const float*)d_in[1];
    float*       outp   = (float*)d_out;
    (void)in_sizes; (void)n_in; (void)out_size;

    ctc_kernel<<<CTC_B, 32>>>(y_true, y_pred, outp);
}

// round 6
// speedup vs baseline: 3.6399x; 3.6399x over previous
#include <cuda_runtime.h>
#include <cstdint>

// CTC loss, probability-domain forward DP, per-lane block-float exponents.
// R6 = R5 with the smem-ring WAR race fixed: lookahead is RCH-1 (7), so the
// chunk issued at the top of iteration c targets slot (c-1)&7, whose reads
// finished in iteration c-1 (separated by full-mask shfl convergence points).
// B=512, T=512, C=128, L=64, S=129, blank=127. One warp per batch element.

#define CTC_B 512
#define CTC_T 512
#define CTC_C 128
#define CTC_L 64
#define CH    8                 // rows (time steps) per chunk = rescale period
#define RCH   8                 // ring slots (usable pipeline depth = RCH-1)
#define LA    (RCH - 1)         // lookahead chunks in flight
#define NCH   (CTC_T / CH)      // 64 chunks

__global__ __launch_bounds__(32) void ctc_kernel(
    const int* __restrict__ y_true,
    const float* __restrict__ y_pred,
    float* __restrict__ out)
{
    __shared__ float ring[RCH * CH * CTC_C];   // 32 KB

    const float EPS = 1e-7f;
    const unsigned FULL = 0xffffffffu;
    const int b    = blockIdx.x;
    const int lane = threadIdx.x;

    // labels for odd states s=4l+1 (label 2l) and s=4l+3 (label 2l+1)
    const int* lrow = y_true + b * CTC_L;
    const int lab1 = lrow[2 * lane];
    const int lab3 = lrow[2 * lane + 1];
    const int prev1 = (lane > 0) ? lrow[2 * lane - 1] : -1;
    const bool allow1 = (lane > 0) && (lab1 != prev1);
    const bool allow3 = (lab3 != lab1);

    const float* base = y_pred + (size_t)b * CTC_T * CTC_C;
    const unsigned smb = (unsigned)__cvta_generic_to_shared(ring);
    const unsigned lane4 = 4u * lane;

    // Issue one chunk: 8 rows, 1 cp.async.cg 16B per lane per row, 1 commit.
    auto issue_chunk = [&](int c) {
        const unsigned slot = (unsigned)(c & (RCH - 1)) * (CH * CTC_C);
#pragma unroll
        for (int r = 0; r < CH; ++r) {
            const float* src = base + (size_t)(c * CH + r) * CTC_C + lane4;
            const unsigned dst = smb + (slot + (unsigned)r * CTC_C + lane4) * 4u;
            asm volatile("cp.async.cg.shared.global [%0], [%1], 16;"
                         :: "r"(dst), "l"(src));
        }
        asm volatile("cp.async.commit_group;");
    };

    // Prologue: fill LA chunks (slots 0..6).
#pragma unroll
    for (int c = 0; c < LA; ++c) issue_chunk(c);

    // virtual pre-init: a0=1 on lane 0 makes step t=0 yield the reference init
    float a0 = (lane == 0) ? 1.0f : 0.0f;
    float a1 = 0.0f, a2 = 0.0f, a3 = 0.0f, a4 = 0.0f;
    int   E  = 0;                               // alpha = a * 2^E (per lane)
    float f  = (lane == 0) ? 0.0f : 1.0f;       // neighbor re-basing factor

    for (int c = 0; c < NCH; ++c) {
        // Issue chunk c+LA into slot (c-1)&7 (reads of that slot finished in
        // iteration c-1; all lanes converged via shfl_sync since then).
        if (c + LA < NCH) issue_chunk(c + LA);
        else asm volatile("cp.async.commit_group;");   // keep group accounting uniform

        // committed = c + LA + 1 = c+8 groups; pending <= 7 -> chunk c complete
        asm volatile("cp.async.wait_group 7;");
        __syncwarp();

        // Batch-gather the 3 needed probs for all 8 rows of this chunk (LDS).
        const int cb = (c & (RCH - 1)) * (CH * CTC_C);
        float pb[CH], p1[CH], p3[CH];
#pragma unroll
        for (int j = 0; j < CH; ++j) {
            const int rb = cb + j * CTC_C;
            pb[j] = ring[rb + (CTC_C - 1)] + EPS;   // blank: broadcast LDS
            p1[j] = ring[rb + lab1] + EPS;
            p3[j] = ring[rb + lab3] + EPS;
        }

        // 8 DP steps (pure FADD/FMUL + 1 shfl each).
#pragma unroll
        for (int j = 0; j < CH; ++j) {
            const float am1 = __shfl_up_sync(FULL, a3, 1) * f;   // lane0: f=0

            const float n0 = (a0 + am1) * pb[j];                          // s=4l (blank)
            const float n1 = (a1 + a0 + (allow1 ? am1 : 0.0f)) * p1[j];   // s=4l+1
            const float n2 = (a2 + a1) * pb[j];                           // s=4l+2
            const float n3 = (a3 + a2 + (allow3 ? a1 : 0.0f)) * p3[j];    // s=4l+3
            const float n4 = (a4 + a3) * pb[j];                           // s=128 (lane31)
            a0 = n0; a1 = n1; a2 = n2; a3 = n3; a4 = n4;
        }

        // ---- per-lane power-of-2 rescale (once per chunk = every 8 steps) ----
        {
            float lm = fmaxf(fmaxf(a0, a1), fmaxf(a2, a3));
            lm = fmaxf(lm, a4);
            int e = (int)(__float_as_uint(lm) >> 23) - 127;
            const bool zero = (lm == 0.0f);
            if (zero) e = 0;
            const float sc = __uint_as_float((unsigned)(127 - e) << 23); // 2^-e
            a0 *= sc; a1 *= sc; a2 *= sc; a3 *= sc; a4 *= sc;
            E += e;
            // all-zero lanes (ahead of the DP wavefront) adopt neighbor's frame
            const int Ep = __shfl_up_sync(FULL, E, 1);
            if (zero && lane > 0) E = Ep;
            // neighbor re-basing factor for the next chunk
            const int Ep2 = __shfl_up_sync(FULL, E, 1);
            int d = Ep2 - E;
            d = max(-126, min(126, d));
            f = __uint_as_float((unsigned)(127 + d) << 23);  // 2^d
            if (lane == 0) f = 0.0f;
        }
    }

    if (lane == 31) {
        // P_total = alpha_{T-1}[S-1] + alpha_{T-1}[S-2] = (a4 + a3) * 2^E
        const float p = a4 + a3;
        out[b] = -(__logf(p) + (float)E * 0.69314718055994530942f);
    }
}

extern "C" void kernel_launch(void* const* d_in, const int* in_sizes, int n_in,
                              void* d_out, int out_size) {
    const int*   y_true = (const int*)d_in[0];
    const float* y_pred = (const float*)d_in[1];
    float*       outp   = (float*)d_out;
    (void)in_sizes; (void)n_in; (void)out_size;

    ctc_kernel<<<CTC_B, 32>>>(y_true, y_pred, outp);
}